// round 16
// baseline (speedup 1.0000x reference)
#include <cuda_runtime.h>
#include <cuda_fp16.h>
#include <cstdint>

#define KDIM 1024
#define IDIM 64
#define ODIM 1024
#define THREADS 256
#define KC 32                   // k per chunk
#define NCHUNK (KDIM / KC)      // 32 per i; 64 per CTA (i-pair)
#define NCH2 (2 * NCHUNK)

// 64B-row tiles, SW64 XOR swizzle (conflict-free for ldmatrix phases)
#define SWZ64(o) ((uint32_t)(o) ^ ((((uint32_t)(o)) >> 3) & 0x30))
#define TILE_A 8192             // A fp16 tile: 128 x 32 fp16
#define TILE_B16 8192           // B fp16 tile: 128 x 32 fp16

#define OFF_A 0                      // 3 buffers: +0, +8192, +16384
#define OFF_B16 (3 * TILE_A)         // 24576: 2 buffers
#define OFF_SCR (OFF_B16 + 2 * TILE_B16)   // 40960: i0 result scratch, 64KB
#define SMEM_DYN (OFF_SCR + 16 * 256 * 16) // 106496 -> 2 CTAs/SM (208KB)

// Pre-converted x: tile (i, ch) = 8 KB at ((i*32+ch)*8192); swizzled
// [b(128) x 32 fp16] rows of 64B.
__device__ unsigned char g_xh[64 * 32 * 8192];

static __device__ __forceinline__ uint32_t smem_u32(const void* p) {
    uint32_t a;
    asm("{ .reg .u64 t; cvta.to.shared.u64 t, %1; cvt.u32.u64 %0, t; }"
        : "=r"(a) : "l"(p));
    return a;
}

static __device__ __forceinline__ void ldm_x4(uint32_t* r, uint32_t addr) {
    asm volatile(
        "ldmatrix.sync.aligned.m8n8.x4.shared.b16 {%0,%1,%2,%3}, [%4];"
        : "=r"(r[0]), "=r"(r[1]), "=r"(r[2]), "=r"(r[3]) : "r"(addr));
}

static __device__ __forceinline__ void mma_f16(float* d, const uint32_t* a,
                                               const uint32_t* b) {
    asm volatile(
        "mma.sync.aligned.m16n8k16.row.col.f32.f16.f16.f32 "
        "{%0,%1,%2,%3}, {%4,%5,%6,%7}, {%8,%9}, {%0,%1,%2,%3};"
        : "+f"(d[0]), "+f"(d[1]), "+f"(d[2]), "+f"(d[3])
        : "r"(a[0]), "r"(a[1]), "r"(a[2]), "r"(a[3]), "r"(b[0]), "r"(b[1]));
}

static __device__ __forceinline__ void cp16(uint32_t saddr, const void* gaddr) {
    asm volatile("cp.async.cg.shared.global [%0], [%1], 16;"
                 :: "r"(saddr), "l"(gaddr));
}

// Pack float4 -> 2 fp16x2 with single-instruction converts.
static __device__ __forceinline__ uint2 pack_hi4(const float4 v) {
    uint2 r;
    asm("cvt.rn.f16x2.f32 %0, %1, %2;" : "=r"(r.x) : "f"(v.y), "f"(v.x));
    asm("cvt.rn.f16x2.f32 %0, %1, %2;" : "=r"(r.y) : "f"(v.w), "f"(v.z));
    return r;
}

// ───────────── pre-pass: x fp32 -> swizzled fp16 tiles (coalesced) ─────────
__global__ void __launch_bounds__(THREADS)
cvt_x_kernel(const float* __restrict__ x) {
    const int i = blockIdx.x;     // 0..63
    const int bb = blockIdx.y;    // 0..7 (16 batch rows each)
    unsigned char* tiles = g_xh + (size_t)i * NCHUNK * TILE_A;
#pragma unroll
    for (int it = 0; it < 16; ++it) {
        int f = threadIdx.x + it * THREADS;   // 0..4095 float4 over [16b x 256c4]
        int b_loc = f >> 8;
        int c4 = f & 255;
        int b = bb * 16 + b_loc;
        const float4 v = *reinterpret_cast<const float4*>(
            x + (size_t)b * (IDIM * KDIM) + (size_t)i * KDIM + c4 * 4);
        int ch = c4 >> 3;
        uint32_t boff = (uint32_t)(b * 64 + (c4 & 7) * 8);
        *reinterpret_cast<uint2*>(tiles + (size_t)ch * TILE_A + SWZ64(boff)) =
            pack_hi4(v);
    }
}

// ───────────── main GEMM ─────────────

static __device__ __forceinline__ void stage_a(uint32_t dst,
                                               const unsigned char* tile) {
#pragma unroll
    for (int it = 0; it < 2; ++it) {
        int g = threadIdx.x + it * THREADS;
        cp16(dst + (uint32_t)(g * 16), tile + (size_t)g * 16);
    }
}

#define LDG_B(bregs, gb)                                                       \
    do {                                                                       \
        _Pragma("unroll") for (int it_ = 0; it_ < 4; ++it_) {                  \
            int f_ = threadIdx.x + it_ * THREADS;                              \
            int row_ = f_ >> 3, c4_ = f_ & 7;                                  \
            (bregs)[it_] = *reinterpret_cast<const float4*>(                   \
                (gb) + (size_t)row_ * 65536 + c4_ * 4);                        \
        }                                                                      \
    } while (0)

#define CVT_B(bregs, sm, dst_off)                                              \
    do {                                                                       \
        _Pragma("unroll") for (int it_ = 0; it_ < 4; ++it_) {                  \
            int f_ = threadIdx.x + it_ * THREADS;                              \
            int row_ = f_ >> 3, c4_ = f_ & 7;                                  \
            *reinterpret_cast<uint2*>((sm) + (dst_off) +                       \
                                      SWZ64(row_ * 64 + c4_ * 8)) =            \
                pack_hi4((bregs)[it_]);                                        \
        }                                                                      \
    } while (0)

__global__ void __launch_bounds__(THREADS, 2)
fl_kernel(const float* __restrict__ w, const float* __restrict__ bias,
          float* __restrict__ out) {
    extern __shared__ char sm[];
    const uint32_t sbase = smem_u32(sm);
    const int tid = threadIdx.x;
    const int wid = tid >> 5;
    const int lid = tid & 31;
    const int warp_m = wid >> 2;   // 0..1 : 64 M rows each
    const int warp_n = wid & 3;    // 0..3 : 32 N cols each
    const int otile = blockIdx.x;  // 0..7
    const int ipair = blockIdx.y;  // 0..31
    const int i0 = ipair * 2;

    // Tile pointers for the two i's
    const unsigned char* xt0 = g_xh + (size_t)i0 * NCHUNK * TILE_A;
    const unsigned char* xt1 = xt0 + (size_t)NCHUNK * TILE_A;
    const float* wbase = w + ((size_t)otile * 128) * (IDIM * KDIM);
    const float* wa0 = wbase + (size_t)i0 * KDIM;
    const float* wa1 = wa0 + KDIM;

    // SMEM scratch for the i0 result: 16 float4 slots per thread.
    float4* scr = reinterpret_cast<float4*>(sm + OFF_SCR);

    float acc[4][4][4];
#pragma unroll
    for (int a = 0; a < 4; ++a)
#pragma unroll
        for (int b = 0; b < 4; ++b)
#pragma unroll
            for (int c = 0; c < 4; ++c) acc[a][b][c] = 0.0f;

    const uint32_t a_row = (uint32_t)(warp_m * 64 + (lid & 15));
    const uint32_t a_cb = (uint32_t)((lid >> 4) * 16);
    const uint32_t b_row = (uint32_t)(warp_n * 32 + ((lid >> 4) << 3) + (lid & 7));
    const uint32_t b_cb = (uint32_t)(((lid >> 3) & 1) * 16);

    // chunk index c in [0, 64): i-part = c>>5, k-chunk = c&31
#define XTILE(c) (((c) >> 5) ? xt1 : xt0) + (size_t)((c) & 31) * TILE_A
#define WPTR(c)  ((((c) >> 5) ? wa1 : wa0) + ((c) & 31) * KC)

    // Prologue: chunks 0,1
    float4 bregs[4];
    stage_a(sbase + OFF_A + 0 * TILE_A, XTILE(0));
    asm volatile("cp.async.commit_group;" ::: "memory");
    stage_a(sbase + OFF_A + 1 * TILE_A, XTILE(1));
    asm volatile("cp.async.commit_group;" ::: "memory");
    LDG_B(bregs, WPTR(0));
    CVT_B(bregs, sm, OFF_B16 + 0 * TILE_B16);
    LDG_B(bregs, WPTR(1));
    asm volatile("cp.async.wait_group 1;" ::: "memory");
    __syncthreads();

    int a_slot = 0;
    for (int c = 0; c < NCH2; ++c) {
        const int a_next2 = (a_slot + 2 >= 3) ? (a_slot - 1) : (a_slot + 2);
        const bool pf = (c + 2 < NCH2);

        if (pf) {
            stage_a(sbase + OFF_A + (uint32_t)(a_next2 * TILE_A), XTILE(c + 2));
            asm volatile("cp.async.commit_group;" ::: "memory");
        }

        const uint32_t abuf = sbase + OFF_A + (uint32_t)(a_slot * TILE_A);
        const uint32_t bbuf = sbase + OFF_B16 + (uint32_t)((c & 1) * TILE_B16);
#pragma unroll
        for (int ks = 0; ks < 2; ++ks) {
            uint32_t ah[4][4], bh[2][4];
#pragma unroll
            for (int mt = 0; mt < 4; ++mt)
                ldm_x4(ah[mt], abuf +
                       SWZ64((a_row + mt * 16) * 64 + ks * 32 + a_cb));
#pragma unroll
            for (int bt = 0; bt < 2; ++bt)
                ldm_x4(bh[bt], bbuf +
                       SWZ64((b_row + bt * 16) * 64 + ks * 32 + b_cb));
#pragma unroll
            for (int mt = 0; mt < 4; ++mt)
#pragma unroll
                for (int nt = 0; nt < 4; ++nt)
                    mma_f16(acc[mt][nt], ah[mt], &bh[nt >> 1][(nt & 1) * 2]);
        }

        // End of i0: dump acc(+bias_i0) to SMEM scratch (conflict-free),
        // reset acc for i1.
        if (c == NCHUNK - 1) {
            const float* bp0 = bias + (size_t)(otile * 128) * IDIM + i0;
#pragma unroll
            for (int mt = 0; mt < 4; ++mt)
#pragma unroll
                for (int nt = 0; nt < 4; ++nt) {
                    int n_l = warp_n * 32 + nt * 8 + 2 * (lid & 3);
                    float b0 = bp0[(size_t)n_l * IDIM];
                    float b1 = bp0[(size_t)(n_l + 1) * IDIM];
                    scr[(mt * 4 + nt) * 256 + tid] =
                        make_float4(acc[mt][nt][0] + b0, acc[mt][nt][1] + b1,
                                    acc[mt][nt][2] + b0, acc[mt][nt][3] + b1);
                    acc[mt][nt][0] = 0.0f; acc[mt][nt][1] = 0.0f;
                    acc[mt][nt][2] = 0.0f; acc[mt][nt][3] = 0.0f;
                }
        }

        if (c + 1 < NCH2) {
            CVT_B(bregs, sm, OFF_B16 + (uint32_t)(((c + 1) & 1) * TILE_B16));
            if (c + 2 < NCH2) {
                LDG_B(bregs, WPTR(c + 2));
            }
        }

        if (pf) {
            asm volatile("cp.async.wait_group 1;" ::: "memory");
        } else {
            asm volatile("cp.async.wait_group 0;" ::: "memory");
        }
        __syncthreads();

        a_slot = (a_slot + 1 >= 3) ? 0 : (a_slot + 1);
    }

    // Epilogue: merge i0 (SMEM scratch) + i1 (acc+bias); streaming 8B stores.
    const float* bp1 = bias + (size_t)(otile * 128) * IDIM + i0 + 1;
#pragma unroll
    for (int mt = 0; mt < 4; ++mt) {
        int m0 = warp_m * 64 + mt * 16 + (lid >> 2);
#pragma unroll
        for (int nt = 0; nt < 4; ++nt) {
            int n_l = warp_n * 32 + nt * 8 + 2 * (lid & 3);
            float b0 = bp1[(size_t)n_l * IDIM];
            float b1 = bp1[(size_t)(n_l + 1) * IDIM];
            const float4 p = scr[(mt * 4 + nt) * 256 + tid];
            float* o0 = out + (size_t)m0 * (ODIM * IDIM) +
                        (size_t)(otile * 128 + n_l) * IDIM + i0;
            __stcs(reinterpret_cast<float2*>(o0),
                   make_float2(p.x, acc[mt][nt][0] + b0));
            __stcs(reinterpret_cast<float2*>(o0 + IDIM),
                   make_float2(p.y, acc[mt][nt][1] + b1));
            float* o8 = o0 + (size_t)8 * (ODIM * IDIM);
            __stcs(reinterpret_cast<float2*>(o8),
                   make_float2(p.z, acc[mt][nt][2] + b0));
            __stcs(reinterpret_cast<float2*>(o8 + IDIM),
                   make_float2(p.w, acc[mt][nt][3] + b1));
        }
    }
}

extern "C" void kernel_launch(void* const* d_in, const int* in_sizes, int n_in,
                              void* d_out, int out_size) {
    (void)in_sizes; (void)n_in; (void)out_size;
    const float* x = (const float*)d_in[0];
    const float* w = (const float*)d_in[1];
    const float* bias = (const float*)d_in[2];
    float* out = (float*)d_out;

    cvt_x_kernel<<<dim3(IDIM, 8), THREADS>>>(x);

    cudaFuncSetAttribute(fl_kernel, cudaFuncAttributeMaxDynamicSharedMemorySize,
                         SMEM_DYN);
    fl_kernel<<<dim3(ODIM / 128, IDIM / 2), THREADS, SMEM_DYN>>>(w, bias, out);
}

// round 17
// speedup vs baseline: 1.1349x; 1.1349x over previous
#include <cuda_runtime.h>
#include <cuda_fp16.h>
#include <cstdint>

#define KDIM 1024
#define IDIM 64
#define ODIM 1024
#define THREADS 256
#define KC 32                   // k per chunk
#define NCHUNK (KDIM / KC)      // 32 per i; 64 per CTA (i-pair)
#define NCH2 (2 * NCHUNK)

// 64B-row tiles, SW64 XOR swizzle (conflict-free for ldmatrix phases)
#define SWZ64(o) ((uint32_t)(o) ^ ((((uint32_t)(o)) >> 3) & 0x30))
#define TILE_A 8192             // A fp16 tile: 128 x 32 fp16
#define TILE_B16 8192           // B fp16 tile: 128 x 32 fp16

#define OFF_A 0                      // 3 buffers: +0, +8192, +16384
#define OFF_B16 (3 * TILE_A)         // 24576: 2 buffers
#define SMEM_DYN (OFF_B16 + 2 * TILE_B16)   // 40960 (small => healthy L1 carveout)

// Pre-converted x: tile (i, ch) = 8 KB at ((i*32+ch)*8192); swizzled
// [b(128) x 32 fp16] rows of 64B.
__device__ unsigned char g_xh[64 * 32 * 8192];
// Fragment-layout result scratch: [otile 8][ipair 32][iidx 2][slot 16][tid 256]
// float4. Written coalesced by fl_kernel, inverted by tr_kernel. 32 MB.
__device__ float4 g_scr[8 * 32 * 2 * 16 * 256];

static __device__ __forceinline__ uint32_t smem_u32(const void* p) {
    uint32_t a;
    asm("{ .reg .u64 t; cvta.to.shared.u64 t, %1; cvt.u32.u64 %0, t; }"
        : "=r"(a) : "l"(p));
    return a;
}

static __device__ __forceinline__ void ldm_x4(uint32_t* r, uint32_t addr) {
    asm volatile(
        "ldmatrix.sync.aligned.m8n8.x4.shared.b16 {%0,%1,%2,%3}, [%4];"
        : "=r"(r[0]), "=r"(r[1]), "=r"(r[2]), "=r"(r[3]) : "r"(addr));
}

static __device__ __forceinline__ void mma_f16(float* d, const uint32_t* a,
                                               const uint32_t* b) {
    asm volatile(
        "mma.sync.aligned.m16n8k16.row.col.f32.f16.f16.f32 "
        "{%0,%1,%2,%3}, {%4,%5,%6,%7}, {%8,%9}, {%0,%1,%2,%3};"
        : "+f"(d[0]), "+f"(d[1]), "+f"(d[2]), "+f"(d[3])
        : "r"(a[0]), "r"(a[1]), "r"(a[2]), "r"(a[3]), "r"(b[0]), "r"(b[1]));
}

static __device__ __forceinline__ void cp16(uint32_t saddr, const void* gaddr) {
    asm volatile("cp.async.cg.shared.global [%0], [%1], 16;"
                 :: "r"(saddr), "l"(gaddr));
}

// Pack float4 -> 2 fp16x2 with single-instruction converts.
static __device__ __forceinline__ uint2 pack_hi4(const float4 v) {
    uint2 r;
    asm("cvt.rn.f16x2.f32 %0, %1, %2;" : "=r"(r.x) : "f"(v.y), "f"(v.x));
    asm("cvt.rn.f16x2.f32 %0, %1, %2;" : "=r"(r.y) : "f"(v.w), "f"(v.z));
    return r;
}

// ───────────── pre-pass: x fp32 -> swizzled fp16 tiles (coalesced) ─────────
__global__ void __launch_bounds__(THREADS)
cvt_x_kernel(const float* __restrict__ x) {
    const int i = blockIdx.x;     // 0..63
    const int bb = blockIdx.y;    // 0..7 (16 batch rows each)
    unsigned char* tiles = g_xh + (size_t)i * NCHUNK * TILE_A;
#pragma unroll
    for (int it = 0; it < 16; ++it) {
        int f = threadIdx.x + it * THREADS;
        int b_loc = f >> 8;
        int c4 = f & 255;
        int b = bb * 16 + b_loc;
        const float4 v = *reinterpret_cast<const float4*>(
            x + (size_t)b * (IDIM * KDIM) + (size_t)i * KDIM + c4 * 4);
        int ch = c4 >> 3;
        uint32_t boff = (uint32_t)(b * 64 + (c4 & 7) * 8);
        *reinterpret_cast<uint2*>(tiles + (size_t)ch * TILE_A + SWZ64(boff)) =
            pack_hi4(v);
    }
}

// ───────────── main GEMM (writes fragment scratch only) ─────────────

static __device__ __forceinline__ void stage_a(uint32_t dst,
                                               const unsigned char* tile) {
#pragma unroll
    for (int it = 0; it < 2; ++it) {
        int g = threadIdx.x + it * THREADS;
        cp16(dst + (uint32_t)(g * 16), tile + (size_t)g * 16);
    }
}

#define LDG_B(bregs, gb)                                                       \
    do {                                                                       \
        _Pragma("unroll") for (int it_ = 0; it_ < 4; ++it_) {                  \
            int f_ = threadIdx.x + it_ * THREADS;                              \
            int row_ = f_ >> 3, c4_ = f_ & 7;                                  \
            (bregs)[it_] = *reinterpret_cast<const float4*>(                   \
                (gb) + (size_t)row_ * 65536 + c4_ * 4);                        \
        }                                                                      \
    } while (0)

#define CVT_B(bregs, sm, dst_off)                                              \
    do {                                                                       \
        _Pragma("unroll") for (int it_ = 0; it_ < 4; ++it_) {                  \
            int f_ = threadIdx.x + it_ * THREADS;                              \
            int row_ = f_ >> 3, c4_ = f_ & 7;                                  \
            *reinterpret_cast<uint2*>((sm) + (dst_off) +                       \
                                      SWZ64(row_ * 64 + c4_ * 8)) =            \
                pack_hi4((bregs)[it_]);                                        \
        }                                                                      \
    } while (0)

__global__ void __launch_bounds__(THREADS, 2)
fl_kernel(const float* __restrict__ w, const float* __restrict__ bias) {
    extern __shared__ char sm[];
    const uint32_t sbase = smem_u32(sm);
    const int tid = threadIdx.x;
    const int wid = tid >> 5;
    const int lid = tid & 31;
    const int warp_m = wid >> 2;   // 0..1 : 64 M rows each
    const int warp_n = wid & 3;    // 0..3 : 32 N cols each
    const int otile = blockIdx.x;  // 0..7
    const int ipair = blockIdx.y;  // 0..31
    const int i0 = ipair * 2;

    const unsigned char* xt0 = g_xh + (size_t)i0 * NCHUNK * TILE_A;
    const unsigned char* xt1 = xt0 + (size_t)NCHUNK * TILE_A;
    const float* wbase = w + ((size_t)otile * 128) * (IDIM * KDIM);
    const float* wa0 = wbase + (size_t)i0 * KDIM;
    const float* wa1 = wa0 + KDIM;

    float4* scr0 = g_scr + ((size_t)(otile * 32 + ipair) * 2 + 0) * 16 * 256;
    float4* scr1 = scr0 + 16 * 256;

    float acc[4][4][4];
#pragma unroll
    for (int a = 0; a < 4; ++a)
#pragma unroll
        for (int b = 0; b < 4; ++b)
#pragma unroll
            for (int c = 0; c < 4; ++c) acc[a][b][c] = 0.0f;

    const uint32_t a_row = (uint32_t)(warp_m * 64 + (lid & 15));
    const uint32_t a_cb = (uint32_t)((lid >> 4) * 16);
    const uint32_t b_row = (uint32_t)(warp_n * 32 + ((lid >> 4) << 3) + (lid & 7));
    const uint32_t b_cb = (uint32_t)(((lid >> 3) & 1) * 16);

#define XTILE(c) (((c) >> 5) ? xt1 : xt0) + (size_t)((c) & 31) * TILE_A
#define WPTR(c)  ((((c) >> 5) ? wa1 : wa0) + ((c) & 31) * KC)

    // Prologue: chunks 0,1
    float4 bregs[4];
    stage_a(sbase + OFF_A + 0 * TILE_A, XTILE(0));
    asm volatile("cp.async.commit_group;" ::: "memory");
    stage_a(sbase + OFF_A + 1 * TILE_A, XTILE(1));
    asm volatile("cp.async.commit_group;" ::: "memory");
    LDG_B(bregs, WPTR(0));
    CVT_B(bregs, sm, OFF_B16 + 0 * TILE_B16);
    LDG_B(bregs, WPTR(1));
    asm volatile("cp.async.wait_group 1;" ::: "memory");
    __syncthreads();

    int a_slot = 0;
    for (int c = 0; c < NCH2; ++c) {
        const int a_next2 = (a_slot + 2 >= 3) ? (a_slot - 1) : (a_slot + 2);
        const bool pf = (c + 2 < NCH2);

        if (pf) {
            stage_a(sbase + OFF_A + (uint32_t)(a_next2 * TILE_A), XTILE(c + 2));
            asm volatile("cp.async.commit_group;" ::: "memory");
        }

        const uint32_t abuf = sbase + OFF_A + (uint32_t)(a_slot * TILE_A);
        const uint32_t bbuf = sbase + OFF_B16 + (uint32_t)((c & 1) * TILE_B16);
#pragma unroll
        for (int ks = 0; ks < 2; ++ks) {
            uint32_t ah[4][4], bh[2][4];
#pragma unroll
            for (int mt = 0; mt < 4; ++mt)
                ldm_x4(ah[mt], abuf +
                       SWZ64((a_row + mt * 16) * 64 + ks * 32 + a_cb));
#pragma unroll
            for (int bt = 0; bt < 2; ++bt)
                ldm_x4(bh[bt], bbuf +
                       SWZ64((b_row + bt * 16) * 64 + ks * 32 + b_cb));
#pragma unroll
            for (int mt = 0; mt < 4; ++mt)
#pragma unroll
                for (int nt = 0; nt < 4; ++nt)
                    mma_f16(acc[mt][nt], ah[mt], &bh[nt >> 1][(nt & 1) * 2]);
        }

        // End of i0: dump acc(+bias_i0) coalesced to scratch, reset acc.
        if (c == NCHUNK - 1) {
            const float* bp0 = bias + (size_t)(otile * 128) * IDIM + i0;
#pragma unroll
            for (int mt = 0; mt < 4; ++mt)
#pragma unroll
                for (int nt = 0; nt < 4; ++nt) {
                    int n_l = warp_n * 32 + nt * 8 + 2 * (lid & 3);
                    float b0 = bp0[(size_t)n_l * IDIM];
                    float b1 = bp0[(size_t)(n_l + 1) * IDIM];
                    scr0[(mt * 4 + nt) * 256 + tid] =
                        make_float4(acc[mt][nt][0] + b0, acc[mt][nt][1] + b1,
                                    acc[mt][nt][2] + b0, acc[mt][nt][3] + b1);
                    acc[mt][nt][0] = 0.0f; acc[mt][nt][1] = 0.0f;
                    acc[mt][nt][2] = 0.0f; acc[mt][nt][3] = 0.0f;
                }
        }

        if (c + 1 < NCH2) {
            CVT_B(bregs, sm, OFF_B16 + (uint32_t)(((c + 1) & 1) * TILE_B16));
            if (c + 2 < NCH2) {
                LDG_B(bregs, WPTR(c + 2));
            }
        }

        if (pf) {
            asm volatile("cp.async.wait_group 1;" ::: "memory");
        } else {
            asm volatile("cp.async.wait_group 0;" ::: "memory");
        }
        __syncthreads();

        a_slot = (a_slot + 1 >= 3) ? 0 : (a_slot + 1);
    }

    // Epilogue i1: dump acc(+bias_i1) coalesced to scratch. No out writes.
    const float* bp1 = bias + (size_t)(otile * 128) * IDIM + i0 + 1;
#pragma unroll
    for (int mt = 0; mt < 4; ++mt)
#pragma unroll
        for (int nt = 0; nt < 4; ++nt) {
            int n_l = warp_n * 32 + nt * 8 + 2 * (lid & 3);
            float b0 = bp1[(size_t)n_l * IDIM];
            float b1 = bp1[(size_t)(n_l + 1) * IDIM];
            scr1[(mt * 4 + nt) * 256 + tid] =
                make_float4(acc[mt][nt][0] + b0, acc[mt][nt][1] + b1,
                            acc[mt][nt][2] + b0, acc[mt][nt][3] + b1);
        }
}

// ───────────── transpose kernel: fragment scratch -> out ─────────────
// Block = (bq 0..63, otile 0..7); handles b_lo = f(bq) and b_hi = b_lo+8:
// 2 x 32KB of out. SMEM planes [i 64][n 128] padded to stride 130 floats.
#define TPLANE (64 * 130)
#define TSMEM (2 * TPLANE * 4)   // 66560 bytes

__global__ void __launch_bounds__(THREADS)
tr_kernel(float* __restrict__ out) {
    extern __shared__ float ts[];
    const int t = threadIdx.x;
    const int bq = blockIdx.x;    // 0..63
    const int otile = blockIdx.y; // 0..7

    const int wm = bq >> 5;            // warp_m
    const int mt = (bq >> 3) & 3;
    const int lid_hi = bq & 7;         // lid>>2
    const int b_lo = wm * 64 + mt * 16 + lid_hi;   // h=0 row; b_hi = +8

    const int p = t & 63;
    const int grp = t >> 6;
    const int wn = p >> 4;
    const int nt = (p >> 2) & 3;
    const int l2 = p & 3;
    const int tid_src = (wm * 4 + wn) * 32 + lid_hi * 4 + l2;
    const int slot = mt * 4 + nt;

    // Fill: 16 i's per thread; each float4 read serves both b rows.
#pragma unroll
    for (int it = 0; it < 16; ++it) {
        int i = grp * 16 + it;
        int ipair = i >> 1, iidx = i & 1;
        const float4 v = g_scr[((size_t)((otile * 32 + ipair) * 2 + iidx) * 16 +
                                slot) * 256 + tid_src];
        *reinterpret_cast<float2*>(ts + i * 130 + 2 * p) =
            make_float2(v.x, v.y);                       // b_lo plane
        *reinterpret_cast<float2*>(ts + TPLANE + i * 130 + 2 * p) =
            make_float2(v.z, v.w);                       // b_hi plane
    }
    __syncthreads();

    // Drain: coalesced 32 floats per thread per plane.
    const int n = t >> 1;               // 0..127
    const int ibase = (t & 1) * 32;     // 0 or 32
#pragma unroll
    for (int half = 0; half < 2; ++half) {
        const int b = b_lo + 8 * half;
        float* obase = out + (size_t)b * (ODIM * IDIM) + otile * 8192;
        const float* smp = ts + half * TPLANE;
#pragma unroll
        for (int v4 = 0; v4 < 8; ++v4) {
            float4 o;
            o.x = smp[(ibase + v4 * 4 + 0) * 130 + n];
            o.y = smp[(ibase + v4 * 4 + 1) * 130 + n];
            o.z = smp[(ibase + v4 * 4 + 2) * 130 + n];
            o.w = smp[(ibase + v4 * 4 + 3) * 130 + n];
            *reinterpret_cast<float4*>(obase + n * 64 + ibase + v4 * 4) = o;
        }
    }
}

extern "C" void kernel_launch(void* const* d_in, const int* in_sizes, int n_in,
                              void* d_out, int out_size) {
    (void)in_sizes; (void)n_in; (void)out_size;
    const float* x = (const float*)d_in[0];
    const float* w = (const float*)d_in[1];
    const float* bias = (const float*)d_in[2];
    float* out = (float*)d_out;

    cvt_x_kernel<<<dim3(IDIM, 8), THREADS>>>(x);

    cudaFuncSetAttribute(fl_kernel, cudaFuncAttributeMaxDynamicSharedMemorySize,
                         SMEM_DYN);
    fl_kernel<<<dim3(ODIM / 128, IDIM / 2), THREADS, SMEM_DYN>>>(w, bias);

    cudaFuncSetAttribute(tr_kernel, cudaFuncAttributeMaxDynamicSharedMemorySize,
                         TSMEM);
    tr_kernel<<<dim3(64, 8), THREADS, TSMEM>>>(out);
}